// round 5
// baseline (speedup 1.0000x reference)
#include <cuda_runtime.h>
#include <math.h>

#define N_ENT 100000
#define N_REL 64
#define EDIM  64
#define KN    32
#define BSZ   1024
#define SLOPE 0.2f

// Scratch (device globals; no allocation allowed)
__device__ float g_scale[N_ENT];                    // per-row normalization scale (400 KB)
__device__ __align__(16) float g_RwT[EDIM * N_REL]; // [f][r] = sum_e Rn[r][e] * att_w1[f][64+e]

// ---------------------------------------------------------------------------
// Fused prep kernel:
//   blocks [0, 782): per-row scale of E — 2 threads/row, 8x float4 each
//   block  782     : Rn = normalize(R); g_RwT[f][r] = Rn[r]·att_w1[f][64:]
// ---------------------------------------------------------------------------
__global__ void prep_kernel(const float* __restrict__ E,
                            const float* __restrict__ R,
                            const float* __restrict__ att_w1) {
    const int tid = threadIdx.x;  // 256
    if (blockIdx.x < 782) {
        const int row  = blockIdx.x * 128 + (tid >> 1);
        const int part = tid & 1;
        if (row >= N_ENT) return;
        const float4* Ev = reinterpret_cast<const float4*>(E + row * 64) + part * 8;
        float ss = 0.f;
        #pragma unroll
        for (int i = 0; i < 8; i++) {
            float4 v = Ev[i];
            ss += v.x*v.x + v.y*v.y + v.z*v.z + v.w*v.w;
        }
        ss += __shfl_xor_sync(0xffffffffu, ss, 1, 2);
        if (part == 0) {
            float n = sqrtf(ss);
            g_scale[row] = (n > 1.0f) ? (1.0f / (n + 1e-7f)) : 1.0f;
        }
        return;
    }
    // ---- prep Rw (single block) ----
    __shared__ __align__(16) float sRn[N_REL * EDIM];
    __shared__ float sScale[N_REL];
    for (int i = tid; i < N_REL * EDIM; i += 256) sRn[i] = R[i];
    __syncthreads();
    if (tid < N_REL) {
        const float4* rv = reinterpret_cast<const float4*>(sRn + tid * EDIM);
        float ss = 0.f;
        #pragma unroll
        for (int e4 = 0; e4 < 16; e4++) {
            float4 v = rv[e4];
            ss += v.x*v.x + v.y*v.y + v.z*v.z + v.w*v.w;
        }
        float n = sqrtf(ss);
        sScale[tid] = (n > 1.0f) ? (1.0f / (n + 1e-7f)) : 1.0f;
    }
    __syncthreads();
    for (int i = tid; i < N_REL * EDIM; i += 256) sRn[i] *= sScale[i >> 6];
    __syncthreads();
    for (int i = tid; i < EDIM * N_REL; i += 256) {
        int f = i >> 6, r = i & 63;
        const float4* w  = reinterpret_cast<const float4*>(att_w1 + f * 128 + 64);
        const float4* rn = reinterpret_cast<const float4*>(sRn + r * 64);
        float a0 = 0.f, a1 = 0.f;
        #pragma unroll
        for (int e4 = 0; e4 < 16; e4 += 2) {
            float4 rv = rn[e4],     wv = w[e4];
            float4 rw = rn[e4 + 1], ww = w[e4 + 1];
            a0 += rv.x*wv.x + rv.y*wv.y + rv.z*wv.z + rv.w*wv.w;
            a1 += rw.x*ww.x + rw.y*ww.y + rw.z*ww.z + rw.w*ww.w;
        }
        g_RwT[i] = a0 + a1;  // [f][r]
    }
}

// ---------------------------------------------------------------------------
// Main kernel: TWO batch elements per block, 256 threads, 4 blocks/SM
// ---------------------------------------------------------------------------
__global__ __launch_bounds__(256, 4) void kgan_main_kernel(
    const int*   __restrict__ entity_idx,
    const int*   __restrict__ adj_entity,
    const int*   __restrict__ adj_relation,
    const float* __restrict__ E,
    const float* __restrict__ att_w1,
    const float* __restrict__ att_w2,
    const float* __restrict__ att_w3,
    const float* __restrict__ wx_w,
    const float* __restrict__ wx_b,
    const float* __restrict__ wc_w,
    const float* __restrict__ wc_b,
    float*       __restrict__ out)
{
    __shared__ __align__(16) float sRwT[64 * 64];   // [f][r]
    __shared__ __align__(16) float sW2 [64 * 64];   // permuted float4 slots: g*16 + j*2 + fh
    __shared__ float sw3[64];
    __shared__ float sh[2][64], shsum[2][64], sbh1[2][64], sbh2[2][64];
    __shared__ int   sEnt1[2][32], sRel1[2][32];
    __shared__ float sScale1[2][32];
    __shared__ float sA[2][96];
    __shared__ float sWk[2][32], sE2[2][64];
    __shared__ __align__(16) int sPacked[2][1024];  // ei | (ri<<17); aliased later
    __shared__ __align__(16) float2 sAggP2[8][32];  // per-warp hop2 partials
    __shared__ float sSP[8];

    const int tid  = threadIdx.x;
    const int b0   = blockIdx.x * 2;
    const int lane = tid & 31;
    const int warp = tid >> 5;

    // alias region (valid only after gather sync): per-b [agg1|agg2|v1|v2]
    float* aliasF = reinterpret_cast<float*>(sPacked);

    // ================= phase A: weight tables + level-1 indices ============
    {
        const float4* Rs = reinterpret_cast<const float4*>(g_RwT);
        float4*       Rd = reinterpret_cast<float4*>(sRwT);
        const float4* Ws = reinterpret_cast<const float4*>(att_w2);
        float4*       Wd = reinterpret_cast<float4*>(sW2);
        #pragma unroll
        for (int q = 0; q < 4; q++) {
            int i = tid + q * 256;
            Rd[i] = Rs[i];
            int g = i >> 4, i4 = i & 15;
            Wd[g * 16 + ((i4 & 7) << 1) + (i4 >> 3)] = Ws[i];  // interleave f-halves
        }
    }
    if (tid < 64) sw3[tid] = att_w3[tid];
    if (tid < 64) {
        int bb = tid >> 5, k = tid & 31;
        int eidx = entity_idx[b0 + bb];
        int e1 = adj_entity[eidx * KN + k];
        sEnt1[bb][k]   = e1;
        sRel1[bb][k]   = adj_relation[eidx * KN + k];
        sScale1[bb][k] = g_scale[e1];
    }
    if (tid < 128) {
        int bb = tid >> 6, f = tid & 63;
        int eidx = entity_idx[b0 + bb];
        sh[bb][f] = E[eidx * 64 + f] * g_scale[eidx];
    }
    __syncthreads();

    // ====== phase B: stage hop-2 adjacency (packed) + hsum =================
    #pragma unroll
    for (int q = 0; q < 8; q++) {
        int p  = tid + q * 256;        // 0..2047
        int bb = p >> 10;
        int pi = p & 1023;
        int n1 = pi >> 5, k = pi & 31;
        int base = sEnt1[bb][n1] * KN;
        int ei = adj_entity[base + k];
        int ri = adj_relation[base + k];
        sPacked[bb][pi] = ei | (ri << 17);
    }
    if (tid < 128) {
        int bb = tid >> 6, f = tid & 63;
        float s = 0.f;
        #pragma unroll 8
        for (int k = 0; k < 32; k++)
            s += sScale1[bb][k] * E[sEnt1[bb][k] * 64 + f];
        shsum[bb][f] = s;
    }
    __syncthreads();

    // ====== phase C: bh = {h,hsum} @ w1h^T — all 256 threads ===============
    {
        int vec = tid >> 6;            // 0: b0-h, 1: b0-hsum, 2: b1-h, 3: b1-hsum
        int bb  = vec >> 1;
        int f   = tid & 63;
        const float*  src = (vec & 1) ? shsum[bb] : sh[bb];
        const float4* w   = reinterpret_cast<const float4*>(att_w1 + f * 128);
        float a0 = 0.f, a1 = 0.f;
        #pragma unroll
        for (int e4 = 0; e4 < 16; e4 += 2) {
            float4 wv = w[e4], ww = w[e4 + 1];
            a0 += wv.x * src[e4*4]   + wv.y * src[e4*4+1]
                + wv.z * src[e4*4+2] + wv.w * src[e4*4+3];
            a1 += ww.x * src[e4*4+4] + ww.y * src[e4*4+5]
                + ww.z * src[e4*4+6] + ww.w * src[e4*4+7];
        }
        if (vec & 1) sbh2[bb][f] = a0 + a1; else sbh1[bb][f] = a0 + a1;
    }
    __syncthreads();

    // ====== stage 7: 192 tasks x 2 f-halves = 384 thread-tasks, 2 passes ===
    #pragma unroll
    for (int pass = 0; pass < 2; pass++) {
        int tt = tid + pass * 256;
        if (tt < 384) {
            const int task = tt >> 1;
            const int fh   = tt & 1;
            const int bb   = (task >= 96);
            const int t96  = task - bb * 96;
            const float* bh = (t96 < 32) ? sbh1[bb] : sbh2[bb];
            const int    r  = (t96 < 32) ? sRel1[bb][t96] : (t96 - 32);

            float hid[32];
            #pragma unroll
            for (int j = 0; j < 8; j++) {
                #pragma unroll
                for (int c = 0; c < 4; c++) {
                    int f = fh * 32 + j * 4 + c;
                    hid[j * 4 + c] = fmaxf(bh[f] + sRwT[f * 64 + r], 0.0f);
                }
            }
            const float4* w2 = reinterpret_cast<const float4*>(sW2);
            float a = 0.0f;
            #pragma unroll
            for (int gb = 0; gb < 64; gb += 8) {
                float dp[8];
                #pragma unroll
                for (int u = 0; u < 8; u++) {
                    const int g = gb + u;
                    float d0 = 0.f, d1 = 0.f;
                    #pragma unroll
                    for (int j = 0; j < 8; j += 2) {
                        float4 wa = w2[g * 16 + j * 2 + fh];
                        float4 wb = w2[g * 16 + (j + 1) * 2 + fh];
                        d0 += wa.x * hid[j*4]   + wa.y * hid[j*4+1]
                            + wa.z * hid[j*4+2] + wa.w * hid[j*4+3];
                        d1 += wb.x * hid[j*4+4] + wb.y * hid[j*4+5]
                            + wb.z * hid[j*4+6] + wb.w * hid[j*4+7];
                    }
                    dp[u] = d0 + d1;
                }
                #pragma unroll
                for (int u = 0; u < 8; u++)
                    dp[u] += __shfl_xor_sync(0xffffffffu, dp[u], 1);
                #pragma unroll
                for (int u = 0; u < 8; u++)
                    a += sw3[gb + u] * fmaxf(dp[u], 0.0f);
            }
            if (fh == 0) sA[bb][t96] = a;
        }
    }
    __syncthreads();

    // ====== exp(sigmoid(a)) tables =========================================
    if (tid < 192) {
        int bb = (tid >= 96);
        int t  = tid - bb * 96;
        float e = expf(1.0f / (1.0f + expf(-sA[bb][t])));
        if (t < 32) sWk[bb][t] = e; else sE2[bb][t - 32] = e;
    }
    __syncthreads();

    // ====== hop-2 gather: warps 0-3 -> b0, warps 4-7 -> b1; 256 pairs each =
    {
        const int bb    = warp >> 2;
        const int pbase = (warp & 3) * 256;
        float accx = 0.f, accy = 0.f, esum = 0.f;
        const float2* E2 = reinterpret_cast<const float2*>(E);
        #pragma unroll 8
        for (int t = 0; t < 256; t++) {
            int   pk  = sPacked[bb][pbase + t];   // broadcast LDS
            int   idx = pk & 0x1FFFF;
            float e   = sE2[bb][pk >> 17];        // broadcast LDS
            esum += e;
            float wt  = e * g_scale[idx];         // warp-uniform L2 LDG.32
            float2 v  = E2[idx * 32 + lane];
            accx += wt * v.x;
            accy += wt * v.y;
        }
        // NOTE: every lane accumulated the SAME 256-pair sum (broadcast reads)
        // -> esum is already this warp's full denominator partial. No reduction!
        if (lane == 0) sSP[warp] = esum;
        sAggP2[warp][lane] = make_float2(accx, accy);
    }
    __syncthreads();   // protects sPacked -> alias transition

    // ====== hop-1 agg + hop-2 combine (tid<128) -> alias region ============
    if (tid < 128) {
        int bb = tid >> 6, f = tid & 63;
        float s1 = 0.f, acc1 = 0.f;
        #pragma unroll 8
        for (int k = 0; k < 32; k++) {
            float w = sWk[bb][k];
            s1   += w;
            acc1 += w * sScale1[bb][k] * E[sEnt1[bb][k] * 64 + f];
        }
        const float* aggp = reinterpret_cast<const float*>(sAggP2);
        float s2 = sSP[bb*4] + sSP[bb*4+1] + sSP[bb*4+2] + sSP[bb*4+3];
        float acc2 = 0.f;
        #pragma unroll
        for (int w = 0; w < 4; w++) acc2 += aggp[(bb * 4 + w) * 64 + f];
        aliasF[bb * 1024 + f]      = acc1 / s1;   // agg1
        aliasF[bb * 1024 + 64 + f] = acc2 / s2;   // agg2
    }
    __syncthreads();

    // ====== v1/v2 = leaky(agg @ wx_w^T + wx_b) =============================
    if (tid < 128) {
        int bb = tid >> 6, f = tid & 63;
        const float* agg1 = aliasF + bb * 1024;
        const float* agg2 = agg1 + 64;
        const float4* w = reinterpret_cast<const float4*>(wx_w + f * 64);
        float a1 = wx_b[f], a2 = a1;
        #pragma unroll
        for (int e4 = 0; e4 < 16; e4++) {
            float4 wv = w[e4];
            a1 += wv.x * agg1[e4*4]   + wv.y * agg1[e4*4+1]
                + wv.z * agg1[e4*4+2] + wv.w * agg1[e4*4+3];
            a2 += wv.x * agg2[e4*4]   + wv.y * agg2[e4*4+1]
                + wv.z * agg2[e4*4+2] + wv.w * agg2[e4*4+3];
        }
        aliasF[bb * 1024 + 128 + f] = (a1 >= 0.f) ? a1 : SLOPE * a1;  // v1
        aliasF[bb * 1024 + 192 + f] = (a2 >= 0.f) ? a2 : SLOPE * a2;  // v2
    }
    __syncthreads();

    // ====== emb1/emb2 = leaky([x, v] @ wc_w^T + wc_b) + h out ==============
    if (tid < 128) {
        int bb = tid >> 6, f = tid & 63;
        const float* v1 = aliasF + bb * 1024 + 128;
        const float* v2 = v1 + 64;
        const float4* w = reinterpret_cast<const float4*>(wc_w + f * 128);
        float a1 = wc_b[f], a2 = a1;
        #pragma unroll
        for (int e4 = 0; e4 < 16; e4++) {
            float4 wv = w[e4];
            a1 += wv.x * sh[bb][e4*4]      + wv.y * sh[bb][e4*4+1]
                + wv.z * sh[bb][e4*4+2]    + wv.w * sh[bb][e4*4+3];
            a2 += wv.x * shsum[bb][e4*4]   + wv.y * shsum[bb][e4*4+1]
                + wv.z * shsum[bb][e4*4+2] + wv.w * shsum[bb][e4*4+3];
        }
        #pragma unroll
        for (int e4 = 0; e4 < 16; e4++) {
            float4 wv = w[16 + e4];
            a1 += wv.x * v1[e4*4]   + wv.y * v1[e4*4+1]
                + wv.z * v1[e4*4+2] + wv.w * v1[e4*4+3];
            a2 += wv.x * v2[e4*4]   + wv.y * v2[e4*4+1]
                + wv.z * v2[e4*4+2] + wv.w * v2[e4*4+3];
        }
        int ob = (b0 + bb) * 192;
        out[ob + 64 + f]  = (a1 >= 0.f) ? a1 : SLOPE * a1;
        out[ob + f]       = (a2 >= 0.f) ? a2 : SLOPE * a2;
        out[ob + 128 + f] = sh[bb][f];
    }
}

extern "C" void kernel_launch(void* const* d_in, const int* in_sizes, int n_in,
                              void* d_out, int out_size) {
    const int*   entity_idx   = (const int*)  d_in[0];
    const int*   adj_entity   = (const int*)  d_in[1];
    const int*   adj_relation = (const int*)  d_in[2];
    const float* E            = (const float*)d_in[3];
    const float* R            = (const float*)d_in[4];
    const float* att_w1       = (const float*)d_in[5];
    const float* att_w2       = (const float*)d_in[6];
    const float* att_w3       = (const float*)d_in[7];
    const float* wx_w         = (const float*)d_in[8];
    const float* wx_b         = (const float*)d_in[9];
    const float* wc_w         = (const float*)d_in[10];
    const float* wc_b         = (const float*)d_in[11];
    float* out = (float*)d_out;

    prep_kernel<<<783, 256>>>(E, R, att_w1);
    kgan_main_kernel<<<BSZ / 2, 256>>>(entity_idx, adj_entity, adj_relation, E,
                                       att_w1, att_w2, att_w3,
                                       wx_w, wx_b, wc_w, wc_b, out);
}

// round 6
// speedup vs baseline: 2.5767x; 2.5767x over previous
#include <cuda_runtime.h>
#include <math.h>

#define N_ENT 100000
#define N_REL 64
#define EDIM  64
#define KN    32
#define BSZ   1024
#define SLOPE 0.2f

// Scratch (device globals; no allocation allowed)
__device__ float g_scale[N_ENT];                    // per-row normalization scale (400 KB)
__device__ __align__(16) float g_RwT[EDIM * N_REL]; // [f][r] = sum_e Rn[r][e] * att_w1[f][64+e]

// ---- packed fp32x2 helpers (sm_103a FFMA2 only reachable via PTX) ----------
__device__ __forceinline__ unsigned long long fma2(unsigned long long a,
                                                   unsigned long long b,
                                                   unsigned long long c) {
    unsigned long long d;
    asm("fma.rn.f32x2 %0, %1, %2, %3;" : "=l"(d) : "l"(a), "l"(b), "l"(c));
    return d;
}
__device__ __forceinline__ unsigned long long pack2(float lo, float hi) {
    unsigned long long d;
    asm("mov.b64 %0, {%1, %2};" : "=l"(d) : "f"(lo), "f"(hi));
    return d;
}
__device__ __forceinline__ float2 unpack2(unsigned long long v) {
    float2 r;
    asm("mov.b64 {%0, %1}, %2;" : "=f"(r.x), "=f"(r.y) : "l"(v));
    return r;
}

// ---------------------------------------------------------------------------
// Fused prep kernel:
//   blocks [0, 1563): per-row scale of E — 4 threads/row, 4x float4 each
//   block  1563     : Rn = normalize(R); g_RwT[f][r] = Rn[r]·att_w1[f][64:]
// ---------------------------------------------------------------------------
__global__ void prep_kernel(const float* __restrict__ E,
                            const float* __restrict__ R,
                            const float* __restrict__ att_w1) {
    const int tid = threadIdx.x;  // 256
    if (blockIdx.x < 1563) {
        const int row  = blockIdx.x * 64 + (tid >> 2);
        const int part = tid & 3;
        if (row >= N_ENT) return;
        const float4* Ev = reinterpret_cast<const float4*>(E + row * 64) + part * 4;
        float ss = 0.f;
        #pragma unroll
        for (int i = 0; i < 4; i++) {
            float4 v = Ev[i];
            ss += v.x*v.x + v.y*v.y + v.z*v.z + v.w*v.w;
        }
        ss += __shfl_xor_sync(0xffffffffu, ss, 2, 4);
        ss += __shfl_xor_sync(0xffffffffu, ss, 1, 4);
        if (part == 0) {
            float n = sqrtf(ss);
            g_scale[row] = (n > 1.0f) ? (1.0f / (n + 1e-7f)) : 1.0f;
        }
        return;
    }
    // ---- prep Rw (single block) ----
    __shared__ __align__(16) float sRn[N_REL * EDIM];
    __shared__ float sScale[N_REL];
    for (int i = tid; i < N_REL * EDIM; i += 256) sRn[i] = R[i];
    __syncthreads();
    if (tid < N_REL) {
        const float4* rv = reinterpret_cast<const float4*>(sRn + tid * EDIM);
        float ss = 0.f;
        #pragma unroll
        for (int e4 = 0; e4 < 16; e4++) {
            float4 v = rv[e4];
            ss += v.x*v.x + v.y*v.y + v.z*v.z + v.w*v.w;
        }
        float n = sqrtf(ss);
        sScale[tid] = (n > 1.0f) ? (1.0f / (n + 1e-7f)) : 1.0f;
    }
    __syncthreads();
    for (int i = tid; i < N_REL * EDIM; i += 256) sRn[i] *= sScale[i >> 6];
    __syncthreads();
    for (int i = tid; i < EDIM * N_REL; i += 256) {
        int f = i >> 6, r = i & 63;
        const float4* w  = reinterpret_cast<const float4*>(att_w1 + f * 128 + 64);
        const float4* rn = reinterpret_cast<const float4*>(sRn + r * 64);
        float a0 = 0.f, a1 = 0.f;
        #pragma unroll
        for (int e4 = 0; e4 < 16; e4 += 2) {
            float4 rv = rn[e4],     wv = w[e4];
            float4 rw = rn[e4 + 1], ww = w[e4 + 1];
            a0 += rv.x*wv.x + rv.y*wv.y + rv.z*wv.z + rv.w*wv.w;
            a1 += rw.x*ww.x + rw.y*ww.y + rw.z*ww.z + rw.w*ww.w;
        }
        g_RwT[i] = a0 + a1;  // [f][r]
    }
}

// ---------------------------------------------------------------------------
// Main kernel: one block per batch element, 256 threads, 4 blocks/SM
// (structure identical to the proven R3 version; stage-7 inner product
//  rewritten with packed f32x2 FMA, exp -> __expf)
// ---------------------------------------------------------------------------
__global__ __launch_bounds__(256, 4) void kgan_main_kernel(
    const int*   __restrict__ entity_idx,
    const int*   __restrict__ adj_entity,
    const int*   __restrict__ adj_relation,
    const float* __restrict__ E,
    const float* __restrict__ att_w1,
    const float* __restrict__ att_w2,
    const float* __restrict__ att_w3,
    const float* __restrict__ wx_w,
    const float* __restrict__ wx_b,
    const float* __restrict__ wc_w,
    const float* __restrict__ wc_b,
    float*       __restrict__ out)
{
    __shared__ __align__(16) float sRwT[64 * 64];   // [f][r]
    __shared__ __align__(16) float sW2 [64 * 64];   // permuted float4 slots: g*16 + j*2 + fh
    __shared__ float sw3[64];
    __shared__ float sh[64], shsum[64], sbh1[64], sbh2[64];
    __shared__ int   sEnt1[32], sRel1[32];
    __shared__ float sScale1[32];
    __shared__ float sA[96];                        // attention pre-activations
    __shared__ float sWk[32], sWks[32], sE2[64];
    __shared__ int   sPacked[1024];                 // ei | (ri<<17)
    __shared__ float sWt[1024];                     // e(rel)*scale(ent)
    __shared__ __align__(16) float2 sAggP2[8 * 32]; // per-warp hop2 partial agg
    __shared__ float sSP[8];
    __shared__ float sAgg1[64], sAgg2[64], sV1[64], sV2[64];

    const int tid  = threadIdx.x;
    const int b    = blockIdx.x;
    const int lane = tid & 31;
    const int warp = tid >> 5;

    // ================= phase A: weight tables + level-1 indices ============
    {
        const float4* Rs = reinterpret_cast<const float4*>(g_RwT);
        float4*       Rd = reinterpret_cast<float4*>(sRwT);
        const float4* Ws = reinterpret_cast<const float4*>(att_w2);
        float4*       Wd = reinterpret_cast<float4*>(sW2);
        #pragma unroll
        for (int q = 0; q < 4; q++) {
            int i = tid + q * 256;
            Rd[i] = Rs[i];
            int g = i >> 4, i4 = i & 15;
            Wd[g * 16 + ((i4 & 7) << 1) + (i4 >> 3)] = Ws[i];  // interleave f-halves
        }
    }
    if (tid < 64) sw3[tid] = att_w3[tid];
    const int eidx = entity_idx[b];
    if (tid < 32) {
        int e1 = adj_entity[eidx * KN + tid];
        sEnt1[tid]   = e1;
        sRel1[tid]   = adj_relation[eidx * KN + tid];
        sScale1[tid] = g_scale[e1];
    }
    if (tid < 64) sh[tid] = E[eidx * 64 + tid] * g_scale[eidx];
    __syncthreads();

    // ====== phase B: stage hop-2 adjacency (packed) + hsum =================
    #pragma unroll
    for (int q = 0; q < 4; q++) {
        int p  = tid + q * 256;
        int n1 = p >> 5, k = p & 31;
        int base = sEnt1[n1] * KN;
        int ei = adj_entity[base + k];
        int ri = adj_relation[base + k];
        sPacked[p] = ei | (ri << 17);
    }
    if (tid < 64) {
        float s = 0.f;
        #pragma unroll 8
        for (int k = 0; k < 32; k++)
            s += sScale1[k] * E[sEnt1[k] * 64 + tid];
        shsum[tid] = s;
    }
    __syncthreads();

    // ====== phase C: bh1 = h @ w1h^T, bh2 = hsum @ w1h^T ===================
    if (tid < 128) {
        int f = tid & 63;
        const float*  src = (tid < 64) ? sh : shsum;
        const float4* w   = reinterpret_cast<const float4*>(att_w1 + f * 128);
        float a0 = 0.f, a1 = 0.f;
        #pragma unroll
        for (int e4 = 0; e4 < 16; e4 += 2) {
            float4 wv = w[e4], ww = w[e4 + 1];
            a0 += wv.x * src[e4*4]   + wv.y * src[e4*4+1]
                + wv.z * src[e4*4+2] + wv.w * src[e4*4+3];
            a1 += ww.x * src[e4*4+4] + ww.y * src[e4*4+5]
                + ww.z * src[e4*4+6] + ww.w * src[e4*4+7];
        }
        if (tid < 64) sbh1[f] = a0 + a1; else sbh2[f] = a0 + a1;
    }
    __syncthreads();

    // ====== stage 7: attention tasks (96 tasks x 2 f-halves = 192 threads) =
    // task < 32: hop1 neighbor k (r = rel1[k], bh1); task in [32,96): hop2 rel r-32
    if (tid < 192) {
        const int task = tid >> 1;
        const int fh   = tid & 1;
        const float* bh = (task < 32) ? sbh1 : sbh2;
        const int    r  = (task < 32) ? sRel1[task] : (task - 32);

        // hidden vector for this f-half, packed as 16 x f32x2 (32 regs)
        unsigned long long hidp[16];
        #pragma unroll
        for (int m = 0; m < 16; m++) {
            int f = fh * 32 + m * 2;
            float h0 = fmaxf(bh[f]     + sRwT[f * 64 + r],       0.0f);
            float h1 = fmaxf(bh[f + 1] + sRwT[(f + 1) * 64 + r], 0.0f);
            hidp[m] = pack2(h0, h1);
        }

        const ulonglong2* w2 = reinterpret_cast<const ulonglong2*>(sW2);
        float a = 0.0f;
        #pragma unroll
        for (int gb = 0; gb < 64; gb += 8) {
            float dp[8];
            #pragma unroll
            for (int u = 0; u < 8; u++) {
                const int g = gb + u;
                unsigned long long dpp = 0ull;   // (0.0f, 0.0f)
                #pragma unroll
                for (int j = 0; j < 8; j++) {
                    ulonglong2 wv = w2[g * 16 + j * 2 + fh];  // float4 slot as 2x f32x2
                    dpp = fma2(wv.x, hidp[j * 2],     dpp);
                    dpp = fma2(wv.y, hidp[j * 2 + 1], dpp);
                }
                float2 dd = unpack2(dpp);
                dp[u] = dd.x + dd.y;
            }
            #pragma unroll
            for (int u = 0; u < 8; u++)
                dp[u] += __shfl_xor_sync(0xffffffffu, dp[u], 1);
            #pragma unroll
            for (int u = 0; u < 8; u++)
                a += sw3[gb + u] * fmaxf(dp[u], 0.0f);
        }
        if (fh == 0) sA[task] = a;
    }
    __syncthreads();

    // ====== exp(sigmoid(a)) tables =========================================
    if (tid < 96) {
        float e = __expf(1.0f / (1.0f + __expf(-sA[tid])));
        if (tid < 32) { sWk[tid] = e; sWks[tid] = e * sScale1[tid]; }
        else          sE2[tid - 32] = e;
    }
    __syncthreads();

    // ====== hop-2 pair weights + softmax denominator =======================
    float esum = 0.f;
    #pragma unroll
    for (int q = 0; q < 4; q++) {
        int p  = tid + q * 256;
        int pk = sPacked[p];
        int ei = pk & 0x1FFFF;
        int ri = pk >> 17;
        float e = sE2[ri];
        esum  += e;
        sWt[p] = e * g_scale[ei];
    }
    #pragma unroll
    for (int o = 16; o > 0; o >>= 1) esum += __shfl_xor_sync(0xffffffffu, esum, o);
    if (lane == 0) sSP[warp] = esum;
    __syncthreads();

    // ====== hop-2 gather: warp handles 128 pairs, lanes split feature dim ==
    {
        float accx = 0.f, accy = 0.f;
        const float2* E2 = reinterpret_cast<const float2*>(E);
        const int pbase = warp * 128;
        #pragma unroll 8
        for (int t = 0; t < 128; t++) {
            int   pk = sPacked[pbase + t];   // broadcast LDS
            float wt = sWt[pbase + t];       // broadcast LDS
            int  idx = pk & 0x1FFFF;
            float2 v = E2[idx * 32 + lane];
            accx += wt * v.x;
            accy += wt * v.y;
        }
        sAggP2[warp * 32 + lane] = make_float2(accx, accy);
    }
    // hop-1 aggregation (same threads, independent data)
    if (tid < 64) {
        float s1 = 0.f, acc = 0.f;
        #pragma unroll
        for (int k = 0; k < 32; k++) s1 += sWk[k];
        #pragma unroll 8
        for (int k = 0; k < 32; k++)
            acc += sWks[k] * E[sEnt1[k] * 64 + tid];
        sAgg1[tid] = acc / s1;
    }
    __syncthreads();

    // ====== combine hop-2 partials =========================================
    if (tid < 64) {
        const float* aggp = reinterpret_cast<const float*>(sAggP2);
        float s2 = 0.f;
        #pragma unroll
        for (int w = 0; w < 8; w++) s2 += sSP[w];
        float acc = 0.f;
        #pragma unroll
        for (int w = 0; w < 8; w++) acc += aggp[w * 64 + tid];
        sAgg2[tid] = acc / s2;
    }
    __syncthreads();

    // ====== v1/v2 = leaky(agg @ wx_w^T + wx_b) (fused, wx row loaded once) =
    if (tid < 64) {
        const float4* w = reinterpret_cast<const float4*>(wx_w + tid * 64);
        float a1 = wx_b[tid], a2 = a1;
        #pragma unroll
        for (int e4 = 0; e4 < 16; e4++) {
            float4 wv = w[e4];
            a1 += wv.x * sAgg1[e4*4]   + wv.y * sAgg1[e4*4+1]
                + wv.z * sAgg1[e4*4+2] + wv.w * sAgg1[e4*4+3];
            a2 += wv.x * sAgg2[e4*4]   + wv.y * sAgg2[e4*4+1]
                + wv.z * sAgg2[e4*4+2] + wv.w * sAgg2[e4*4+3];
        }
        sV1[tid] = (a1 >= 0.f) ? a1 : SLOPE * a1;
        sV2[tid] = (a2 >= 0.f) ? a2 : SLOPE * a2;
    }
    __syncthreads();

    // ====== emb1/emb2 = leaky([x, v] @ wc_w^T + wc_b) (fused) + h out ======
    if (tid < 64) {
        const float4* w = reinterpret_cast<const float4*>(wc_w + tid * 128);
        float a1 = wc_b[tid], a2 = a1;
        #pragma unroll
        for (int e4 = 0; e4 < 16; e4++) {
            float4 wv = w[e4];
            a1 += wv.x * sh[e4*4]      + wv.y * sh[e4*4+1]
                + wv.z * sh[e4*4+2]    + wv.w * sh[e4*4+3];
            a2 += wv.x * shsum[e4*4]   + wv.y * shsum[e4*4+1]
                + wv.z * shsum[e4*4+2] + wv.w * shsum[e4*4+3];
        }
        #pragma unroll
        for (int e4 = 0; e4 < 16; e4++) {
            float4 wv = w[16 + e4];
            a1 += wv.x * sV1[e4*4]   + wv.y * sV1[e4*4+1]
                + wv.z * sV1[e4*4+2] + wv.w * sV1[e4*4+3];
            a2 += wv.x * sV2[e4*4]   + wv.y * sV2[e4*4+1]
                + wv.z * sV2[e4*4+2] + wv.w * sV2[e4*4+3];
        }
        out[b * 192 + 64 + tid]  = (a1 >= 0.f) ? a1 : SLOPE * a1;
        out[b * 192 + tid]       = (a2 >= 0.f) ? a2 : SLOPE * a2;
        out[b * 192 + 128 + tid] = sh[tid];
    }
}

extern "C" void kernel_launch(void* const* d_in, const int* in_sizes, int n_in,
                              void* d_out, int out_size) {
    const int*   entity_idx   = (const int*)  d_in[0];
    const int*   adj_entity   = (const int*)  d_in[1];
    const int*   adj_relation = (const int*)  d_in[2];
    const float* E            = (const float*)d_in[3];
    const float* R            = (const float*)d_in[4];
    const float* att_w1       = (const float*)d_in[5];
    const float* att_w2       = (const float*)d_in[6];
    const float* att_w3       = (const float*)d_in[7];
    const float* wx_w         = (const float*)d_in[8];
    const float* wx_b         = (const float*)d_in[9];
    const float* wc_w         = (const float*)d_in[10];
    const float* wc_b         = (const float*)d_in[11];
    float* out = (float*)d_out;

    prep_kernel<<<1564, 256>>>(E, R, att_w1);
    kgan_main_kernel<<<BSZ, 256>>>(entity_idx, adj_entity, adj_relation, E,
                                   att_w1, att_w2, att_w3,
                                   wx_w, wx_b, wc_w, wc_b, out);
}

// round 7
// speedup vs baseline: 2.9094x; 1.1291x over previous
#include <cuda_runtime.h>
#include <math.h>

#define N_ENT 100000
#define N_REL 64
#define EDIM  64
#define KN    32
#define BSZ   1024
#define SLOPE 0.2f

// Scratch (device globals; no allocation allowed)
__device__ float g_scale[N_ENT];                    // per-row normalization scale (400 KB)
__device__ __align__(16) float g_RwT[EDIM * N_REL]; // [f][r] = sum_e Rn[r][e] * att_w1[f][64+e]

// ---- packed fp32x2 helpers (sm_103a FFMA2 only reachable via PTX) ----------
__device__ __forceinline__ unsigned long long fma2(unsigned long long a,
                                                   unsigned long long b,
                                                   unsigned long long c) {
    unsigned long long d;
    asm("fma.rn.f32x2 %0, %1, %2, %3;" : "=l"(d) : "l"(a), "l"(b), "l"(c));
    return d;
}
__device__ __forceinline__ unsigned long long pack2(float lo, float hi) {
    unsigned long long d;
    asm("mov.b64 %0, {%1, %2};" : "=l"(d) : "f"(lo), "f"(hi));
    return d;
}
__device__ __forceinline__ float2 unpack2(unsigned long long v) {
    float2 r;
    asm("mov.b64 {%0, %1}, %2;" : "=f"(r.x), "=f"(r.y) : "l"(v));
    return r;
}

// ---------------------------------------------------------------------------
// Fused prep kernel:
//   blocks [0, 782): per-row scale of E — 2 threads/row, 8x float4 each (MLP 8)
//   blocks [782, 798): Rw slices — each block computes 256 of the 4096 outputs
// ---------------------------------------------------------------------------
__global__ void prep_kernel(const float* __restrict__ E,
                            const float* __restrict__ R,
                            const float* __restrict__ att_w1) {
    const int tid = threadIdx.x;  // 256
    if (blockIdx.x < 782) {
        const int row  = blockIdx.x * 128 + (tid >> 1);
        const int part = tid & 1;
        if (row >= N_ENT) return;
        const float4* Ev = reinterpret_cast<const float4*>(E + row * 64) + part * 8;
        float ss = 0.f;
        #pragma unroll
        for (int i = 0; i < 8; i++) {
            float4 v = Ev[i];
            ss += v.x*v.x + v.y*v.y + v.z*v.z + v.w*v.w;
        }
        ss += __shfl_xor_sync(0xffffffffu, ss, 1, 2);
        if (part == 0) {
            float n = sqrtf(ss);
            g_scale[row] = (n > 1.0f) ? (1.0f / (n + 1e-7f)) : 1.0f;
        }
        return;
    }
    // ---- Rw slice (16 blocks, 256 outputs each) ----
    __shared__ __align__(16) float sRn[N_REL * EDIM];
    __shared__ float sScale[N_REL];
    const int slice = blockIdx.x - 782;
    for (int i = tid; i < N_REL * EDIM; i += 256) sRn[i] = R[i];
    __syncthreads();
    if (tid < N_REL) {
        const float4* rv = reinterpret_cast<const float4*>(sRn + tid * EDIM);
        float ss = 0.f;
        #pragma unroll
        for (int e4 = 0; e4 < 16; e4++) {
            float4 v = rv[e4];
            ss += v.x*v.x + v.y*v.y + v.z*v.z + v.w*v.w;
        }
        float n = sqrtf(ss);
        sScale[tid] = (n > 1.0f) ? (1.0f / (n + 1e-7f)) : 1.0f;
    }
    __syncthreads();
    for (int i = tid; i < N_REL * EDIM; i += 256) sRn[i] *= sScale[i >> 6];
    __syncthreads();
    {
        int i = slice * 256 + tid;       // output index
        int f = i >> 6, r = i & 63;
        const float4* w  = reinterpret_cast<const float4*>(att_w1 + f * 128 + 64);
        const float4* rn = reinterpret_cast<const float4*>(sRn + r * 64);
        float a0 = 0.f, a1 = 0.f;
        #pragma unroll
        for (int e4 = 0; e4 < 16; e4 += 2) {
            float4 rv = rn[e4],     wv = w[e4];
            float4 rw = rn[e4 + 1], ww = w[e4 + 1];
            a0 += rv.x*wv.x + rv.y*wv.y + rv.z*wv.z + rv.w*wv.w;
            a1 += rw.x*ww.x + rw.y*ww.y + rw.z*ww.z + rw.w*ww.w;
        }
        g_RwT[i] = a0 + a1;  // [f][r]
    }
}

// ---------------------------------------------------------------------------
// Main kernel: one block per batch element, 128 threads, 8 blocks/SM
// (RwT read from global through L1; sW2 stays in shared; post-gather buffers
//  aliased onto dead sPacked/sWt regions)
// ---------------------------------------------------------------------------
__global__ __launch_bounds__(128, 8) void kgan_main_kernel(
    const int*   __restrict__ entity_idx,
    const int*   __restrict__ adj_entity,
    const int*   __restrict__ adj_relation,
    const float* __restrict__ E,
    const float* __restrict__ att_w1,
    const float* __restrict__ att_w2,
    const float* __restrict__ att_w3,
    const float* __restrict__ wx_w,
    const float* __restrict__ wx_b,
    const float* __restrict__ wc_w,
    const float* __restrict__ wc_b,
    float*       __restrict__ out)
{
    __shared__ __align__(16) float sW2 [64 * 64];   // permuted float4 slots: g*16 + j*2 + fh
    __shared__ __align__(16) int   sPacked[1024];   // ei | (ri<<17); aliased after gather
    __shared__ __align__(16) float sWt[1024];       // pair weights; per-warp tail reused for partials
    __shared__ float sw3[64];
    __shared__ float sh[64], shsum[64], sbh1[64], sbh2[64];
    __shared__ int   sEnt1[32], sRel1[32];
    __shared__ float sScale1[32];
    __shared__ float sA[96];
    __shared__ float sWk[32], sWks[32], sE2[64];
    __shared__ float sSP[4];

    const int tid  = threadIdx.x;
    const int b    = blockIdx.x;
    const int lane = tid & 31;
    const int warp = tid >> 5;

    // alias region (valid only after gather sync): [agg1|agg2|v1|v2]
    float* aliasF = reinterpret_cast<float*>(sPacked);

    // ================= phase A: W2 table + level-1 indices =================
    {
        const float4* Ws = reinterpret_cast<const float4*>(att_w2);
        float4*       Wd = reinterpret_cast<float4*>(sW2);
        #pragma unroll
        for (int q = 0; q < 8; q++) {
            int i = tid + q * 128;
            int g = i >> 4, i4 = i & 15;
            Wd[g * 16 + ((i4 & 7) << 1) + (i4 >> 3)] = Ws[i];  // interleave f-halves
        }
    }
    if (tid < 64) sw3[tid] = att_w3[tid];
    const int eidx = entity_idx[b];
    if (tid < 32) {
        int e1 = adj_entity[eidx * KN + tid];
        sEnt1[tid]   = e1;
        sRel1[tid]   = adj_relation[eidx * KN + tid];
        sScale1[tid] = g_scale[e1];
    }
    if (tid < 64) sh[tid] = E[eidx * 64 + tid] * g_scale[eidx];
    __syncthreads();

    // ====== phase B: stage hop-2 adjacency (packed) + hsum =================
    #pragma unroll
    for (int q = 0; q < 8; q++) {
        int p  = tid + q * 128;
        int n1 = p >> 5, k = p & 31;
        int base = sEnt1[n1] * KN;
        int ei = adj_entity[base + k];
        int ri = adj_relation[base + k];
        sPacked[p] = ei | (ri << 17);
    }
    if (tid < 64) {
        float s = 0.f;
        #pragma unroll 8
        for (int k = 0; k < 32; k++)
            s += sScale1[k] * E[sEnt1[k] * 64 + tid];
        shsum[tid] = s;
    }
    __syncthreads();

    // ====== phase C: bh1 = h @ w1h^T, bh2 = hsum @ w1h^T (128 threads) =====
    {
        int f = tid & 63;
        const float*  src = (tid < 64) ? sh : shsum;
        const float4* w   = reinterpret_cast<const float4*>(att_w1 + f * 128);
        float a0 = 0.f, a1 = 0.f;
        #pragma unroll
        for (int e4 = 0; e4 < 16; e4 += 2) {
            float4 wv = w[e4], ww = w[e4 + 1];
            a0 += wv.x * src[e4*4]   + wv.y * src[e4*4+1]
                + wv.z * src[e4*4+2] + wv.w * src[e4*4+3];
            a1 += ww.x * src[e4*4+4] + ww.y * src[e4*4+5]
                + ww.z * src[e4*4+6] + ww.w * src[e4*4+7];
        }
        if (tid < 64) sbh1[f] = a0 + a1; else sbh2[f] = a0 + a1;
    }
    __syncthreads();

    // ====== stage 7: 96 tasks x 2 f-halves = 192 thread-tasks, 2 passes ====
    #pragma unroll
    for (int pass = 0; pass < 2; pass++) {
        int tt = tid + pass * 128;
        if (tt < 192) {
            const int task = tt >> 1;
            const int fh   = tt & 1;
            const float* bh = (task < 32) ? sbh1 : sbh2;
            const int    r  = (task < 32) ? sRel1[task] : (task - 32);

            // hidden vector for this f-half, packed as 16 x f32x2
            unsigned long long hidp[16];
            #pragma unroll
            for (int m = 0; m < 16; m++) {
                int f = fh * 32 + m * 2;
                float h0 = fmaxf(bh[f]     + __ldg(&g_RwT[f * 64 + r]),       0.0f);
                float h1 = fmaxf(bh[f + 1] + __ldg(&g_RwT[(f + 1) * 64 + r]), 0.0f);
                hidp[m] = pack2(h0, h1);
            }

            const ulonglong2* w2 = reinterpret_cast<const ulonglong2*>(sW2);
            float a = 0.0f;
            #pragma unroll
            for (int gb = 0; gb < 64; gb += 8) {
                float dp[8];
                #pragma unroll
                for (int u = 0; u < 8; u++) {
                    const int g = gb + u;
                    unsigned long long dpp = 0ull;
                    #pragma unroll
                    for (int j = 0; j < 8; j++) {
                        ulonglong2 wv = w2[g * 16 + j * 2 + fh];
                        dpp = fma2(wv.x, hidp[j * 2],     dpp);
                        dpp = fma2(wv.y, hidp[j * 2 + 1], dpp);
                    }
                    float2 dd = unpack2(dpp);
                    dp[u] = dd.x + dd.y;
                }
                #pragma unroll
                for (int u = 0; u < 8; u++)
                    dp[u] += __shfl_xor_sync(0xffffffffu, dp[u], 1);
                #pragma unroll
                for (int u = 0; u < 8; u++)
                    a += sw3[gb + u] * fmaxf(dp[u], 0.0f);
            }
            if (fh == 0) sA[task] = a;
        }
    }
    __syncthreads();

    // ====== exp(sigmoid(a)) tables =========================================
    if (tid < 96) {
        float e = __expf(1.0f / (1.0f + __expf(-sA[tid])));
        if (tid < 32) { sWk[tid] = e; sWks[tid] = e * sScale1[tid]; }
        else          sE2[tid - 32] = e;
    }
    __syncthreads();

    // ====== hop-2 pair weights + softmax denominator =======================
    float esum = 0.f;
    #pragma unroll
    for (int q = 0; q < 8; q++) {
        int p  = tid + q * 128;
        int pk = sPacked[p];
        int ei = pk & 0x1FFFF;
        int ri = pk >> 17;
        float e = sE2[ri];
        esum  += e;
        sWt[p] = e * g_scale[ei];
    }
    #pragma unroll
    for (int o = 16; o > 0; o >>= 1) esum += __shfl_xor_sync(0xffffffffu, esum, o);
    if (lane == 0) sSP[warp] = esum;
    __syncthreads();

    // ====== hop-2 gather: warp handles 256 pairs, lanes split feature dim ==
    {
        float accx = 0.f, accy = 0.f;
        const float2* E2 = reinterpret_cast<const float2*>(E);
        const int pbase = warp * 256;
        #pragma unroll 8
        for (int t = 0; t < 256; t++) {
            int   pk = sPacked[pbase + t];   // broadcast LDS
            float wt = sWt[pbase + t];       // broadcast LDS
            int  idx = pk & 0x1FFFF;
            float2 v = E2[idx * 32 + lane];
            accx += wt * v.x;
            accy += wt * v.y;
        }
        // write partials into this warp's OWN dead sWt segment (no race:
        // each warp reads only [pbase, pbase+256) and is done with it)
        sWt[pbase + lane * 2]     = accx;    // feature 2*lane
        sWt[pbase + lane * 2 + 1] = accy;    // feature 2*lane+1
    }
    __syncthreads();   // gather done; sPacked/sWt transition to alias use

    // ====== hop-1 agg (tid<64) + hop-2 combine (tid in [64,128)) ===========
    if (tid < 64) {
        float s1 = 0.f, acc = 0.f;
        #pragma unroll
        for (int k = 0; k < 32; k++) s1 += sWk[k];
        #pragma unroll 8
        for (int k = 0; k < 32; k++)
            acc += sWks[k] * E[sEnt1[k] * 64 + tid];
        aliasF[tid] = acc / s1;              // agg1
    } else {
        int f = tid - 64;
        float s2 = sSP[0] + sSP[1] + sSP[2] + sSP[3];
        float acc = sWt[f] + sWt[256 + f] + sWt[512 + f] + sWt[768 + f];
        aliasF[64 + f] = acc / s2;           // agg2
    }
    __syncthreads();

    // ====== v1/v2 = leaky(agg @ wx_w^T + wx_b) (fused) =====================
    if (tid < 64) {
        const float* agg1 = aliasF;
        const float* agg2 = aliasF + 64;
        const float4* w = reinterpret_cast<const float4*>(wx_w + tid * 64);
        float a1 = wx_b[tid], a2 = a1;
        #pragma unroll
        for (int e4 = 0; e4 < 16; e4++) {
            float4 wv = w[e4];
            a1 += wv.x * agg1[e4*4]   + wv.y * agg1[e4*4+1]
                + wv.z * agg1[e4*4+2] + wv.w * agg1[e4*4+3];
            a2 += wv.x * agg2[e4*4]   + wv.y * agg2[e4*4+1]
                + wv.z * agg2[e4*4+2] + wv.w * agg2[e4*4+3];
        }
        aliasF[128 + tid] = (a1 >= 0.f) ? a1 : SLOPE * a1;  // v1
        aliasF[192 + tid] = (a2 >= 0.f) ? a2 : SLOPE * a2;  // v2
    }
    __syncthreads();

    // ====== emb1/emb2 = leaky([x, v] @ wc_w^T + wc_b) (fused) + h out ======
    if (tid < 64) {
        const float* v1 = aliasF + 128;
        const float* v2 = aliasF + 192;
        const float4* w = reinterpret_cast<const float4*>(wc_w + tid * 128);
        float a1 = wc_b[tid], a2 = a1;
        #pragma unroll
        for (int e4 = 0; e4 < 16; e4++) {
            float4 wv = w[e4];
            a1 += wv.x * sh[e4*4]      + wv.y * sh[e4*4+1]
                + wv.z * sh[e4*4+2]    + wv.w * sh[e4*4+3];
            a2 += wv.x * shsum[e4*4]   + wv.y * shsum[e4*4+1]
                + wv.z * shsum[e4*4+2] + wv.w * shsum[e4*4+3];
        }
        #pragma unroll
        for (int e4 = 0; e4 < 16; e4++) {
            float4 wv = w[16 + e4];
            a1 += wv.x * v1[e4*4]   + wv.y * v1[e4*4+1]
                + wv.z * v1[e4*4+2] + wv.w * v1[e4*4+3];
            a2 += wv.x * v2[e4*4]   + wv.y * v2[e4*4+1]
                + wv.z * v2[e4*4+2] + wv.w * v2[e4*4+3];
        }
        out[b * 192 + 64 + tid]  = (a1 >= 0.f) ? a1 : SLOPE * a1;
        out[b * 192 + tid]       = (a2 >= 0.f) ? a2 : SLOPE * a2;
        out[b * 192 + 128 + tid] = sh[tid];
    }
}

extern "C" void kernel_launch(void* const* d_in, const int* in_sizes, int n_in,
                              void* d_out, int out_size) {
    const int*   entity_idx   = (const int*)  d_in[0];
    const int*   adj_entity   = (const int*)  d_in[1];
    const int*   adj_relation = (const int*)  d_in[2];
    const float* E            = (const float*)d_in[3];
    const float* R            = (const float*)d_in[4];
    const float* att_w1       = (const float*)d_in[5];
    const float* att_w2       = (const float*)d_in[6];
    const float* att_w3       = (const float*)d_in[7];
    const float* wx_w         = (const float*)d_in[8];
    const float* wx_b         = (const float*)d_in[9];
    const float* wc_w         = (const float*)d_in[10];
    const float* wc_b         = (const float*)d_in[11];
    float* out = (float*)d_out;

    prep_kernel<<<798, 256>>>(E, R, att_w1);
    kgan_main_kernel<<<BSZ, 128>>>(entity_idx, adj_entity, adj_relation, E,
                                   att_w1, att_w2, att_w3,
                                   wx_w, wx_b, wc_w, wc_b, out);
}